// round 3
// baseline (speedup 1.0000x reference)
#include <cuda_runtime.h>
#include <cuda_fp16.h>
#include <cuda_bf16.h>
#include <cstdint>

// Problem constants
#define NN   8192
#define FIN  256
#define FOUT 128

// ---------------- device scratch (no allocation allowed) ----------------
__device__ __half g_hh[NN * FOUT];   // h in fp16 (row-major) for MMA
__device__ float  g_fs2[NN];         // f_src * log2(e)
__device__ float  g_fd2[NN];         // f_dst * log2(e)
__device__ int    g_gmax_o;          // ordered-int encoded max of g_fd2

__device__ __forceinline__ int f2o(float f) {
    int i = __float_as_int(f);
    return i >= 0 ? i : (i ^ 0x7fffffff);
}
__device__ __forceinline__ float o2f(int o) {
    return __int_as_float(o >= 0 ? o : (o ^ 0x7fffffff));
}

__global__ void k_init() { g_gmax_o = (int)0x80000000; }

// ---------------- kernel 1: h = x @ W, f_src/f_dst, global max ----------
// grid 128, block 256. Tile: 64 rows x 128 cols (full FOUT), BK=32.
__global__ __launch_bounds__(256) void k_gemm(
    const float* __restrict__ x, const float* __restrict__ W,
    const float* __restrict__ a_src, const float* __restrict__ a_dst)
{
    __shared__ float pool[8512];
    float* sx = pool;              // [64][33]
    float* sw = pool + 64 * 33;    // [32][128]

    const int tid = threadIdx.x;
    const int ty = tid >> 4, tx = tid & 15;   // 16x16 thread grid, TM=4 TN=8
    const int i0 = blockIdx.x * 64;

    float acc[4][8];
    #pragma unroll
    for (int m = 0; m < 4; m++)
        #pragma unroll
        for (int n = 0; n < 8; n++) acc[m][n] = 0.f;

    for (int k0 = 0; k0 < FIN; k0 += 32) {
        // x tile 64x32 = 512 float4
        #pragma unroll
        for (int l = tid; l < 512; l += 256) {
            int r = l >> 3, c = (l & 7) << 2;
            float4 v = *(const float4*)&x[(size_t)(i0 + r) * FIN + k0 + c];
            sx[r * 33 + c + 0] = v.x; sx[r * 33 + c + 1] = v.y;
            sx[r * 33 + c + 2] = v.z; sx[r * 33 + c + 3] = v.w;
        }
        // W tile 32x128 = 1024 float4
        #pragma unroll
        for (int l = tid; l < 1024; l += 256) {
            int r = l >> 5, c = (l & 31) << 2;
            *(float4*)&sw[r * 128 + c] = *(const float4*)&W[(size_t)(k0 + r) * FOUT + c];
        }
        __syncthreads();
        #pragma unroll
        for (int k = 0; k < 32; k++) {
            float bv[8];
            #pragma unroll
            for (int n = 0; n < 8; n++) bv[n] = sw[k * 128 + tx * 8 + n];
            #pragma unroll
            for (int m = 0; m < 4; m++) {
                float av = sx[(ty * 4 + m) * 33 + k];
                #pragma unroll
                for (int n = 0; n < 8; n++) acc[m][n] += av * bv[n];
            }
        }
        __syncthreads();
    }

    // reuse pool: sh [64][129], sa/sb [128]
    float* sh = pool;
    float* sa = pool + 64 * 129;
    float* sb = sa + 128;
    if (tid < 128) { sa[tid] = a_src[tid]; sb[tid] = a_dst[tid]; }

    #pragma unroll
    for (int m = 0; m < 4; m++) {
        int r = ty * 4 + m;
        int row = i0 + r;
        #pragma unroll
        for (int n = 0; n < 8; n += 2) {
            __half2 hv = __floats2half2_rn(acc[m][n], acc[m][n + 1]);
            *(__half2*)&g_hh[(size_t)row * FOUT + tx * 8 + n] = hv;
            sh[r * 129 + tx * 8 + n]     = acc[m][n];
            sh[r * 129 + tx * 8 + n + 1] = acc[m][n + 1];
        }
    }
    __syncthreads();

    // f dots: 4 threads per row, 32 cols each
    {
        const int r = tid >> 2, q = tid & 3;
        float ds = 0.f, dd = 0.f;
        #pragma unroll
        for (int c = 0; c < 32; c++) {
            float hv = sh[r * 129 + q * 32 + c];
            ds += hv * sa[q * 32 + c];
            dd += hv * sb[q * 32 + c];
        }
        ds += __shfl_down_sync(0xffffffffu, ds, 1);
        ds += __shfl_down_sync(0xffffffffu, ds, 2);
        dd += __shfl_down_sync(0xffffffffu, dd, 1);
        dd += __shfl_down_sync(0xffffffffu, dd, 2);
        if (q == 0) {
            const float L2E = 1.4426950408889634f;
            float fs2v = ds * L2E, fd2v = dd * L2E;
            g_fs2[i0 + r] = fs2v;
            g_fd2[i0 + r] = fd2v;
            atomicMax(&g_gmax_o, f2o(fd2v));
        }
    }
}

// ---------------- kernel 2: fused masked-softmax attention GEMM ---------
// grid 128 (i-tiles of 64 rows), block 256 (8 warps).
// smem: sH [128][136] half @0 (34816B), sP [64][136] half @34816 (17408B),
//       sFd [128] float @52224, sDen [64] float @52736. total 52992 -> 53248.
#define SMEM_MAIN 53248

#define CP_ASYNC16(dst_u32, src_ptr) \
    asm volatile("cp.async.cg.shared.global [%0], [%1], 16;\n" :: "r"(dst_u32), "l"(src_ptr))

__global__ __launch_bounds__(256) void k_main(
    const float* __restrict__ adj, float* __restrict__ out)
{
    extern __shared__ char smem[];
    __half* sH  = (__half*)smem;               // [128][136]
    __half* sP  = (__half*)(smem + 34816);     // [64][136]
    float*  sFd = (float*)(smem + 52224);      // [128]
    float*  sDen= (float*)(smem + 52736);      // [64]

    const int tid  = threadIdx.x;
    const int lane = tid & 31, wid = tid >> 5;
    const int i0 = blockIdx.x * 64;
    const int r = tid >> 2, q = tid & 3;       // P-compute mapping: 4 threads/row

    const float gmax2 = o2f(g_gmax_o);
    const float fs2r  = g_fs2[i0 + r];
    float sm = fs2r + gmax2;
    const float m2 = (sm >= 0.f) ? sm : 0.2f * sm;
    const float* adjrow = adj + (size_t)(i0 + r) * NN + q * 32;

    float denomL = 0.f;

    float C[8][4];
    #pragma unroll
    for (int a = 0; a < 8; a++)
        #pragma unroll
        for (int b = 0; b < 4; b++) C[a][b] = 0.f;

    const int wm = (wid & 3) * 16;   // 4 warp-rows of 16
    const int wn = (wid >> 2) * 64;  // 2 warp-cols of 64

    for (int jt = 0; jt < 64; jt++) {
        const int j0 = jt * 128;
        __syncthreads();   // prev sH/sP fully consumed

        // async load H tile 128x128 half (2048 x 16B)
        #pragma unroll
        for (int l = 0; l < 8; l++) {
            int idx = tid + l * 256;
            int row = idx >> 4, c8 = (idx & 15) << 3;
            uint32_t dst = (uint32_t)__cvta_generic_to_shared(&sH[row * 136 + c8]);
            CP_ASYNC16(dst, &g_hh[(size_t)(j0 + row) * FOUT + c8]);
        }
        asm volatile("cp.async.commit_group;\n" ::: "memory");

        if (tid < 128) sFd[tid] = g_fd2[j0 + tid];
        __syncthreads();   // sFd ready

        // compute P tile (64x128) -> fp16 smem, accumulate denominator
        const float* arow = adjrow + j0;
        #pragma unroll
        for (int it = 0; it < 8; it++) {
            float4 av = __ldcs((const float4*)(arow + it * 4));
            int jc = q * 32 + it * 4;
            float p[4];
            float a4[4] = {av.x, av.y, av.z, av.w};
            #pragma unroll
            for (int u = 0; u < 4; u++) {
                float s2 = fs2r + sFd[jc + u];
                float t = ((s2 >= 0.f) ? s2 : 0.2f * s2) - m2;
                float e;
                asm("ex2.approx.ftz.f32 %0, %1;" : "=f"(e) : "f"(t));
                p[u] = (a4[u] > 0.f) ? e : 0.f;
            }
            __half2 h01 = __floats2half2_rn(p[0], p[1]);
            __half2 h23 = __floats2half2_rn(p[2], p[3]);
            *(__half2*)&sP[r * 136 + jc]     = h01;
            *(__half2*)&sP[r * 136 + jc + 2] = h23;
            float2 f01 = __half22float2(h01);
            float2 f23 = __half22float2(h23);
            denomL += (f01.x + f01.y) + (f23.x + f23.y);
        }

        asm volatile("cp.async.wait_group 0;\n" ::: "memory");
        __syncthreads();   // sP + sH ready

        // MMA: C(64x128) += P(64x128) @ H(128x128), fp16 in, fp32 acc
        #pragma unroll
        for (int kk = 0; kk < 8; kk++) {
            const int k = kk * 16;
            uint32_t a0, a1, a2, a3;
            {
                uint32_t aaddr = (uint32_t)__cvta_generic_to_shared(
                    &sP[(wm + (lane & 15)) * 136 + k + ((lane >> 4) << 3)]);
                asm volatile("ldmatrix.sync.aligned.m8n8.x4.shared.b16 {%0,%1,%2,%3},[%4];\n"
                             : "=r"(a0), "=r"(a1), "=r"(a2), "=r"(a3) : "r"(aaddr));
            }
            #pragma unroll
            for (int nt = 0; nt < 4; nt++) {
                uint32_t b0, b1, b2, b3;
                uint32_t baddr = (uint32_t)__cvta_generic_to_shared(
                    &sH[(k + (lane & 15)) * 136 + wn + nt * 16 + ((lane >> 4) << 3)]);
                asm volatile("ldmatrix.sync.aligned.m8n8.x4.trans.shared.b16 {%0,%1,%2,%3},[%4];\n"
                             : "=r"(b0), "=r"(b1), "=r"(b2), "=r"(b3) : "r"(baddr));
                asm volatile(
                    "mma.sync.aligned.m16n8k16.row.col.f32.f16.f16.f32 "
                    "{%0,%1,%2,%3}, {%4,%5,%6,%7}, {%8,%9}, {%0,%1,%2,%3};\n"
                    : "+f"(C[2*nt][0]), "+f"(C[2*nt][1]), "+f"(C[2*nt][2]), "+f"(C[2*nt][3])
                    : "r"(a0), "r"(a1), "r"(a2), "r"(a3), "r"(b0), "r"(b1));
                asm volatile(
                    "mma.sync.aligned.m16n8k16.row.col.f32.f16.f16.f32 "
                    "{%0,%1,%2,%3}, {%4,%5,%6,%7}, {%8,%9}, {%0,%1,%2,%3};\n"
                    : "+f"(C[2*nt+1][0]), "+f"(C[2*nt+1][1]), "+f"(C[2*nt+1][2]), "+f"(C[2*nt+1][3])
                    : "r"(a0), "r"(a1), "r"(a2), "r"(a3), "r"(b2), "r"(b3));
            }
        }
    }

    // reduce denominators (4 threads per row, lane-aligned groups)
    denomL += __shfl_down_sync(0xffffffffu, denomL, 1);
    denomL += __shfl_down_sync(0xffffffffu, denomL, 2);
    if (q == 0) sDen[r] = denomL;
    __syncthreads();

    // write normalized output
    {
        const int gr = lane >> 2;
        const float inv0 = 1.f / sDen[wm + gr];
        const float inv1 = 1.f / sDen[wm + gr + 8];
        const int row0 = i0 + wm + gr;
        #pragma unroll
        for (int st = 0; st < 8; st++) {
            int col = wn + st * 8 + ((lane & 3) << 1);
            float* o0 = &out[(size_t)row0 * FOUT + col];
            o0[0] = C[st][0] * inv0;
            o0[1] = C[st][1] * inv0;
            float* o1 = o0 + 8 * FOUT;
            o1[0] = C[st][2] * inv1;
            o1[1] = C[st][3] * inv1;
        }
    }
}

// ---------------- launcher ----------------
extern "C" void kernel_launch(void* const* d_in, const int* in_sizes, int n_in,
                              void* d_out, int out_size)
{
    const float* x     = (const float*)d_in[0];
    const float* adj   = (const float*)d_in[1];
    const float* W     = (const float*)d_in[2];
    const float* a_src = (const float*)d_in[3];
    const float* a_dst = (const float*)d_in[4];
    float* out = (float*)d_out;

    cudaFuncSetAttribute(k_main, cudaFuncAttributeMaxDynamicSharedMemorySize, SMEM_MAIN);

    k_init<<<1, 1>>>();
    k_gemm<<<128, 256>>>(x, W, a_src, a_dst);
    k_main<<<128, 256, SMEM_MAIN>>>(adj, out);
}

// round 4
// speedup vs baseline: 2.2651x; 2.2651x over previous
#include <cuda_runtime.h>
#include <cuda_fp16.h>
#include <cuda_bf16.h>
#include <cstdint>

#define NN   8192
#define FIN  256
#define FOUT 128

// ---------------- device scratch ----------------
__device__ __half g_hh[NN * FOUT];     // h fp16
__device__ __half g_xh[NN * FIN];      // x fp16
__device__ __half g_wh[FIN * FOUT];    // W fp16
__device__ float  g_fs2[NN];           // f_src * log2(e)
__device__ float  g_fd2[NN];           // f_dst * log2(e)
__device__ int    g_gmax_o;            // ordered-int max of g_fd2

__device__ __forceinline__ int f2o(float f) {
    int i = __float_as_int(f);
    return i >= 0 ? i : (i ^ 0x7fffffff);
}
__device__ __forceinline__ float o2f(int o) {
    return __int_as_float(o >= 0 ? o : (o ^ 0x7fffffff));
}

#define CP_ASYNC16(dst_u32, src_ptr) \
    asm volatile("cp.async.cg.shared.global [%0], [%1], 16;\n" :: "r"(dst_u32), "l"(src_ptr))

__device__ __forceinline__ void mbar_init(uint32_t addr, uint32_t cnt) {
    asm volatile("mbarrier.init.shared.b64 [%0], %1;\n" :: "r"(addr), "r"(cnt) : "memory");
}
__device__ __forceinline__ void mbar_arrive(uint32_t addr) {
    asm volatile("mbarrier.arrive.shared.b64 _, [%0];\n" :: "r"(addr) : "memory");
}
__device__ __forceinline__ void mbar_wait(uint32_t addr, uint32_t parity) {
    asm volatile(
        "{\n\t.reg .pred P;\n"
        "W_%=:\n\t"
        "mbarrier.try_wait.parity.acquire.cta.shared::cta.b64 P, [%0], %1, 0x989680;\n\t"
        "@P bra D_%=;\n\t"
        "bra W_%=;\n"
        "D_%=:\n\t}"
        :: "r"(addr), "r"(parity) : "memory");
}

// ---------------- kernel 0: fp32 -> fp16 conversions + init ----------------
__global__ __launch_bounds__(256) void k_cvt(const float* __restrict__ x,
                                             const float* __restrict__ W)
{
    int t = blockIdx.x * 256 + threadIdx.x;   // 262144 threads
    const float4* xp = (const float4*)x;
    float4 v0 = xp[t * 2], v1 = xp[t * 2 + 1];
    __half2 h0 = __floats2half2_rn(v0.x, v0.y);
    __half2 h1 = __floats2half2_rn(v0.z, v0.w);
    __half2 h2 = __floats2half2_rn(v1.x, v1.y);
    __half2 h3 = __floats2half2_rn(v1.z, v1.w);
    uint4 pk;
    pk.x = *(uint32_t*)&h0; pk.y = *(uint32_t*)&h1;
    pk.z = *(uint32_t*)&h2; pk.w = *(uint32_t*)&h3;
    *(uint4*)&g_xh[t * 8] = pk;
    if (t < (FIN * FOUT) / 4) {
        float4 w = ((const float4*)W)[t];
        __half2 w0 = __floats2half2_rn(w.x, w.y);
        __half2 w1 = __floats2half2_rn(w.z, w.w);
        uint2 wp; wp.x = *(uint32_t*)&w0; wp.y = *(uint32_t*)&w1;
        *(uint2*)&g_wh[t * 4] = wp;
    }
    if (t == 0) g_gmax_o = (int)0x80000000;
}

// ---------------- kernel 1: h = x @ W (fp16 MMA), f_src/f_dst, global max --
// grid 128 (64-row tiles), block 128 (4 warps, 16 rows each, full 128 cols).
// smem: sX [64][264] half = 33792B, sW [256][136] half = 69632B -> 103424B
#define SMEM_GEMM 103424

__global__ __launch_bounds__(128, 1) void k_gemm(
    const float* __restrict__ a_src, const float* __restrict__ a_dst)
{
    extern __shared__ char smem[];
    __half* sX = (__half*)smem;
    __half* sW = (__half*)(smem + 33792);
    const uint32_t sb = (uint32_t)__cvta_generic_to_shared(smem);

    const int tid = threadIdx.x;
    const int lane = tid & 31, wid = tid >> 5;
    const int i0 = blockIdx.x * 64;

    // load x tile: 64 rows x 256 halves = 2048 16B chunks
    #pragma unroll
    for (int l = 0; l < 16; l++) {
        int idx = tid + l * 128;
        int row = idx >> 5, c8 = idx & 31;
        *(uint4*)&sX[row * 264 + c8 * 8] =
            *(const uint4*)&g_xh[(size_t)(i0 + row) * FIN + c8 * 8];
    }
    // load full W: 256 rows x 128 halves = 4096 chunks
    #pragma unroll
    for (int l = 0; l < 32; l++) {
        int idx = tid + l * 128;
        int row = idx >> 4, c8 = idx & 15;
        *(uint4*)&sW[row * 136 + c8 * 8] =
            *(const uint4*)&g_wh[row * FOUT + c8 * 8];
    }
    __syncthreads();

    float C[16][4];
    #pragma unroll
    for (int a = 0; a < 16; a++)
        #pragma unroll
        for (int b = 0; b < 4; b++) C[a][b] = 0.f;

    const int wm = wid * 16;
    const uint32_t aB = sb + ((wm + (lane & 15)) * 264 + ((lane >> 4) << 3)) * 2;
    const uint32_t bB = sb + 33792 + (((lane & 15)) * 136 + ((lane >> 4) << 3)) * 2;

    #pragma unroll
    for (int kc = 0; kc < 16; kc++) {
        uint32_t a0, a1, a2, a3;
        asm volatile("ldmatrix.sync.aligned.m8n8.x4.shared.b16 {%0,%1,%2,%3},[%4];\n"
                     : "=r"(a0), "=r"(a1), "=r"(a2), "=r"(a3) : "r"(aB + kc * 32));
        #pragma unroll
        for (int nt = 0; nt < 8; nt++) {
            uint32_t b0, b1, b2, b3;
            asm volatile("ldmatrix.sync.aligned.m8n8.x4.trans.shared.b16 {%0,%1,%2,%3},[%4];\n"
                         : "=r"(b0), "=r"(b1), "=r"(b2), "=r"(b3)
                         : "r"(bB + kc * 16 * 272 + nt * 32));
            asm volatile(
                "mma.sync.aligned.m16n8k16.row.col.f32.f16.f16.f32 "
                "{%0,%1,%2,%3}, {%4,%5,%6,%7}, {%8,%9}, {%0,%1,%2,%3};\n"
                : "+f"(C[2*nt][0]), "+f"(C[2*nt][1]), "+f"(C[2*nt][2]), "+f"(C[2*nt][3])
                : "r"(a0), "r"(a1), "r"(a2), "r"(a3), "r"(b0), "r"(b1));
            asm volatile(
                "mma.sync.aligned.m16n8k16.row.col.f32.f16.f16.f32 "
                "{%0,%1,%2,%3}, {%4,%5,%6,%7}, {%8,%9}, {%0,%1,%2,%3};\n"
                : "+f"(C[2*nt+1][0]), "+f"(C[2*nt+1][1]), "+f"(C[2*nt+1][2]), "+f"(C[2*nt+1][3])
                : "r"(a0), "r"(a1), "r"(a2), "r"(a3), "r"(b2), "r"(b3));
        }
    }

    // store h fp16 + compute f dots from fp32 accumulators
    const int g = lane >> 2, q = lane & 3;
    const int r0 = wm + g, r1 = r0 + 8;
    float ds0 = 0.f, dd0 = 0.f, ds1 = 0.f, dd1 = 0.f;
    #pragma unroll
    for (int nt = 0; nt < 16; nt++) {
        int col = nt * 8 + q * 2;
        float as0 = __ldg(a_src + col), as1 = __ldg(a_src + col + 1);
        float ad0 = __ldg(a_dst + col), ad1 = __ldg(a_dst + col + 1);
        ds0 += C[nt][0] * as0 + C[nt][1] * as1;
        dd0 += C[nt][0] * ad0 + C[nt][1] * ad1;
        ds1 += C[nt][2] * as0 + C[nt][3] * as1;
        dd1 += C[nt][2] * ad0 + C[nt][3] * ad1;
        __half2 h0 = __floats2half2_rn(C[nt][0], C[nt][1]);
        __half2 h1 = __floats2half2_rn(C[nt][2], C[nt][3]);
        *(uint32_t*)&g_hh[(size_t)(i0 + r0) * FOUT + col] = *(uint32_t*)&h0;
        *(uint32_t*)&g_hh[(size_t)(i0 + r1) * FOUT + col] = *(uint32_t*)&h1;
    }
    ds0 += __shfl_xor_sync(0xffffffffu, ds0, 1); ds0 += __shfl_xor_sync(0xffffffffu, ds0, 2);
    dd0 += __shfl_xor_sync(0xffffffffu, dd0, 1); dd0 += __shfl_xor_sync(0xffffffffu, dd0, 2);
    ds1 += __shfl_xor_sync(0xffffffffu, ds1, 1); ds1 += __shfl_xor_sync(0xffffffffu, ds1, 2);
    dd1 += __shfl_xor_sync(0xffffffffu, dd1, 1); dd1 += __shfl_xor_sync(0xffffffffu, dd1, 2);
    if (q == 0) {
        const float L2E = 1.4426950408889634f;
        float fs0 = ds0 * L2E, fd0 = dd0 * L2E;
        float fs1 = ds1 * L2E, fd1 = dd1 * L2E;
        g_fs2[i0 + r0] = fs0; g_fd2[i0 + r0] = fd0;
        g_fs2[i0 + r1] = fs1; g_fd2[i0 + r1] = fd1;
        atomicMax(&g_gmax_o, f2o(fd0));
        atomicMax(&g_gmax_o, f2o(fd1));
    }
}

// ---------------- kernel 2: warp-specialized fused attention ---------------
// grid 128 (64-row i-tiles), block 256: warps 0-3 consume (MMA), 4-7 produce.
// smem layout (bytes):
//   sH[2]:  0      + s*34816   (128x136 half each)
//   sP[2]:  69632  + s*17408   (64x136 half each)
//   sDen:   104448 (64 float)
//   mbFull: 104704 + s*8,  mbEmpty: 104720 + s*8
#define SMEM_MAIN 104736

__global__ __launch_bounds__(256, 1) void k_main(
    const float* __restrict__ adj, float* __restrict__ out)
{
    extern __shared__ char smem[];
    const uint32_t sb = (uint32_t)__cvta_generic_to_shared(smem);
    __half* sP0 = (__half*)(smem + 69632);
    float*  sDen = (float*)(smem + 104448);
    const uint32_t mbF = sb + 104704;
    const uint32_t mbE = sb + 104720;

    const int tid = threadIdx.x;
    const int lane = tid & 31, wid = tid >> 5;
    const int i0 = blockIdx.x * 64;

    if (tid == 0) {
        mbar_init(mbF, 128); mbar_init(mbF + 8, 128);
        mbar_init(mbE, 128); mbar_init(mbE + 8, 128);
    }
    __syncthreads();

    float C[16][4];
    const int wm = (wid & 3) * 16;

    if (wid >= 4) {
        // ---------------- producer ----------------
        const int p = wid - 4;
        const int pt = tid - 128;            // 0..127
        const float gmax2 = o2f(g_gmax_o);
        float fs[16], m2[16], den[16];
        #pragma unroll
        for (int rr = 0; rr < 16; rr++) {
            float f = g_fs2[i0 + p * 16 + rr];
            fs[rr] = f;
            float sm = f + gmax2;
            m2[rr] = (sm >= 0.f) ? sm : 0.2f * sm;
            den[rr] = 0.f;
        }
        const float* adjB = adj + (size_t)(i0 + p * 16) * NN + (lane << 2);

        for (int jt = 0; jt < 64; jt++) {
            const int s = jt & 1;
            const int j0 = jt << 7;
            const uint32_t pe = 1u ^ ((jt >> 1) & 1);

            // buffer-independent loads first (overlap with empty-wait)
            float4 av[16];
            const float* arow = adjB + j0;
            #pragma unroll
            for (int rr = 0; rr < 16; rr++)
                av[rr] = __ldcs((const float4*)(arow + (size_t)rr * NN));
            float4 fd = __ldg((const float4*)(g_fd2 + j0 + (lane << 2)));
            float fdv[4] = {fd.x, fd.y, fd.z, fd.w};

            mbar_wait(mbE + s * 8, pe);

            // async-load H tile into sH[s]
            const __half* hsrc = g_hh + (size_t)j0 * FOUT;
            const uint32_t hdst = sb + s * 34816;
            #pragma unroll
            for (int l = 0; l < 16; l++) {
                int idx = pt + (l << 7);
                int row = idx >> 4, c8 = idx & 15;
                CP_ASYNC16(hdst + (row * 136 + c8 * 8) * 2, hsrc + row * FOUT + c8 * 8);
            }
            asm volatile("cp.async.commit_group;\n" ::: "memory");

            // P tile: rows p*16..+16, cols lane*4..+4
            __half* sPs = sP0 + s * (64 * 136) + p * 16 * 136 + (lane << 2);
            #pragma unroll
            for (int rr = 0; rr < 16; rr++) {
                float p4[4];
                const float* aa = (const float*)&av[rr];
                #pragma unroll
                for (int u = 0; u < 4; u++) {
                    float s2 = fs[rr] + fdv[u];
                    float t = ((s2 >= 0.f) ? s2 : 0.2f * s2) - m2[rr];
                    float e;
                    asm("ex2.approx.ftz.f32 %0, %1;" : "=f"(e) : "f"(t));
                    p4[u] = (aa[u] > 0.f) ? e : 0.f;
                    den[rr] += p4[u];
                }
                __half2 h01 = __floats2half2_rn(p4[0], p4[1]);
                __half2 h23 = __floats2half2_rn(p4[2], p4[3]);
                uint2 pk; pk.x = *(uint32_t*)&h01; pk.y = *(uint32_t*)&h23;
                *(uint2*)(sPs + rr * 136) = pk;
            }

            asm volatile("cp.async.wait_group 0;\n" ::: "memory");
            mbar_arrive(mbF + s * 8);
        }
        // reduce denominators across lanes
        #pragma unroll
        for (int rr = 0; rr < 16; rr++) {
            float v = den[rr];
            #pragma unroll
            for (int o = 1; o < 32; o <<= 1) v += __shfl_xor_sync(0xffffffffu, v, o);
            if (lane == 0) sDen[p * 16 + rr] = v;
        }
    } else {
        // ---------------- consumer ----------------
        #pragma unroll
        for (int a = 0; a < 16; a++)
            #pragma unroll
            for (int b = 0; b < 4; b++) C[a][b] = 0.f;

        for (int jt = 0; jt < 64; jt++) {
            const int s = jt & 1;
            const uint32_t pf = (jt >> 1) & 1;
            mbar_wait(mbF + s * 8, pf);

            const uint32_t aB = sb + 69632 + s * 17408 +
                ((wm + (lane & 15)) * 136 + ((lane >> 4) << 3)) * 2;
            const uint32_t bB = sb + s * 34816 +
                ((lane & 15) * 136 + ((lane >> 4) << 3)) * 2;

            #pragma unroll
            for (int kk = 0; kk < 8; kk++) {
                uint32_t a0, a1, a2, a3;
                asm volatile("ldmatrix.sync.aligned.m8n8.x4.shared.b16 {%0,%1,%2,%3},[%4];\n"
                             : "=r"(a0), "=r"(a1), "=r"(a2), "=r"(a3) : "r"(aB + kk * 32));
                #pragma unroll
                for (int nt = 0; nt < 8; nt++) {
                    uint32_t b0, b1, b2, b3;
                    asm volatile("ldmatrix.sync.aligned.m8n8.x4.trans.shared.b16 {%0,%1,%2,%3},[%4];\n"
                                 : "=r"(b0), "=r"(b1), "=r"(b2), "=r"(b3)
                                 : "r"(bB + kk * 16 * 272 + nt * 32));
                    asm volatile(
                        "mma.sync.aligned.m16n8k16.row.col.f32.f16.f16.f32 "
                        "{%0,%1,%2,%3}, {%4,%5,%6,%7}, {%8,%9}, {%0,%1,%2,%3};\n"
                        : "+f"(C[2*nt][0]), "+f"(C[2*nt][1]), "+f"(C[2*nt][2]), "+f"(C[2*nt][3])
                        : "r"(a0), "r"(a1), "r"(a2), "r"(a3), "r"(b0), "r"(b1));
                    asm volatile(
                        "mma.sync.aligned.m16n8k16.row.col.f32.f16.f16.f32 "
                        "{%0,%1,%2,%3}, {%4,%5,%6,%7}, {%8,%9}, {%0,%1,%2,%3};\n"
                        : "+f"(C[2*nt+1][0]), "+f"(C[2*nt+1][1]), "+f"(C[2*nt+1][2]), "+f"(C[2*nt+1][3])
                        : "r"(a0), "r"(a1), "r"(a2), "r"(a3), "r"(b2), "r"(b3));
                }
            }
            mbar_arrive(mbE + s * 8);
        }
    }

    __syncthreads();

    if (wid < 4) {
        const int g = lane >> 2;
        const float inv0 = 1.f / sDen[wm + g];
        const float inv1 = 1.f / sDen[wm + g + 8];
        const int row0 = i0 + wm + g;
        #pragma unroll
        for (int nt = 0; nt < 16; nt++) {
            int col = nt * 8 + ((lane & 3) << 1);
            float* o0 = &out[(size_t)row0 * FOUT + col];
            o0[0] = C[nt][0] * inv0;
            o0[1] = C[nt][1] * inv0;
            float* o1 = o0 + 8 * FOUT;
            o1[0] = C[nt][2] * inv1;
            o1[1] = C[nt][3] * inv1;
        }
    }
}

// ---------------- launcher ----------------
extern "C" void kernel_launch(void* const* d_in, const int* in_sizes, int n_in,
                              void* d_out, int out_size)
{
    const float* x     = (const float*)d_in[0];
    const float* adj   = (const float*)d_in[1];
    const float* W     = (const float*)d_in[2];
    const float* a_src = (const float*)d_in[3];
    const float* a_dst = (const float*)d_in[4];
    float* out = (float*)d_out;

    cudaFuncSetAttribute(k_gemm, cudaFuncAttributeMaxDynamicSharedMemorySize, SMEM_GEMM);
    cudaFuncSetAttribute(k_main, cudaFuncAttributeMaxDynamicSharedMemorySize, SMEM_MAIN);

    k_cvt<<<(NN * FIN) / (8 * 256), 256>>>(x, W);
    k_gemm<<<128, 128, SMEM_GEMM>>>(a_src, a_dst);
    k_main<<<128, 256, SMEM_MAIN>>>(adj, out);
}